// round 1
// baseline (speedup 1.0000x reference)
#include <cuda_runtime.h>
#include <cstdint>

// Problem constants
#define NROWS 100000
#define DIN   1024
#define DD    512
#define NG    8
#define GS    12500

// ---------------- scratch (device globals; no allocation allowed) ----------
__device__ float    g_tmid[(size_t)NROWS * DD];   // 204.8 MB
__device__ float    g_scores[NROWS];
__device__ float    g_d[NROWS];
__device__ float    g_tAA[NG * GS];
__device__ float    g_bag[NG * DD];
__device__ unsigned g_maxbits;
__device__ float    g_Z;
__device__ int      g_imax[NG];
__device__ int      g_imin[NG];

// ordered-float encoding for atomicMax over signed floats
__device__ __forceinline__ unsigned enc_f(float f) {
    unsigned u = __float_as_uint(f);
    return (u & 0x80000000u) ? ~u : (u | 0x80000000u);
}
__device__ __forceinline__ float dec_f(unsigned u) {
    u = (u & 0x80000000u) ? (u & 0x7FFFFFFFu) : ~u;
    return __uint_as_float(u);
}

// ---------------- init: zero reductions ------------------------------------
__global__ void init_kernel() {
    int tid = blockIdx.x * blockDim.x + threadIdx.x;
    if (tid == 0) { g_maxbits = 0u; g_Z = 0.f; }
    if (tid < NG * DD) g_bag[tid] = 0.f;
}

// ---------------- GEMM1: tmid = relu(x @ W1) --------------------------------
// 128x128 tile, BK=8, 256 threads, 8x8 microtile
__global__ __launch_bounds__(256, 2)
void gemm1_relu(const float* __restrict__ A, const float* __restrict__ B) {
    __shared__ __align__(16) float As[8][128];
    __shared__ __align__(16) float Bs[8][128];
    const int tid = threadIdx.x;
    const int tx = tid & 15, ty = tid >> 4;
    const int row0 = blockIdx.x * 128;
    const int col0 = blockIdx.y * 128;

    const int arow = tid >> 1;          // 0..127
    const int acol = (tid & 1) * 4;     // 0 or 4
    const int brow = tid >> 5;          // 0..7
    const int bcol = (tid & 31) * 4;    // 0..124
    const bool aval = (row0 + arow) < NROWS;

    float acc[8][8];
#pragma unroll
    for (int r = 0; r < 8; r++)
#pragma unroll
        for (int c = 0; c < 8; c++) acc[r][c] = 0.f;

    for (int kt = 0; kt < DIN / 8; kt++) {
        float4 av = aval ? *(const float4*)&A[(size_t)(row0 + arow) * DIN + kt * 8 + acol]
                         : make_float4(0.f, 0.f, 0.f, 0.f);
        As[acol + 0][arow] = av.x;
        As[acol + 1][arow] = av.y;
        As[acol + 2][arow] = av.z;
        As[acol + 3][arow] = av.w;
        *(float4*)&Bs[brow][bcol] =
            *(const float4*)&B[(size_t)(kt * 8 + brow) * DD + col0 + bcol];
        __syncthreads();
#pragma unroll
        for (int k = 0; k < 8; k++) {
            float ra[8], rb[8];
            *(float4*)&ra[0] = *(float4*)&As[k][ty * 8];
            *(float4*)&ra[4] = *(float4*)&As[k][ty * 8 + 4];
            *(float4*)&rb[0] = *(float4*)&Bs[k][tx * 8];
            *(float4*)&rb[4] = *(float4*)&Bs[k][tx * 8 + 4];
#pragma unroll
            for (int r = 0; r < 8; r++)
#pragma unroll
                for (int c = 0; c < 8; c++)
                    acc[r][c] = fmaf(ra[r], rb[c], acc[r][c]);
        }
        __syncthreads();
    }

#pragma unroll
    for (int r = 0; r < 8; r++) {
        int grow = row0 + ty * 8 + r;
        if (grow < NROWS) {
            float4 v0 = make_float4(fmaxf(acc[r][0], 0.f), fmaxf(acc[r][1], 0.f),
                                    fmaxf(acc[r][2], 0.f), fmaxf(acc[r][3], 0.f));
            float4 v1 = make_float4(fmaxf(acc[r][4], 0.f), fmaxf(acc[r][5], 0.f),
                                    fmaxf(acc[r][6], 0.f), fmaxf(acc[r][7], 0.f));
            *(float4*)&g_tmid[(size_t)grow * DD + col0 + tx * 8] = v0;
            *(float4*)&g_tmid[(size_t)grow * DD + col0 + tx * 8 + 4] = v1;
        }
    }
}

// ---------------- GEMM2 fused: scores + d -----------------------------------
// scores[i] = sum_n tanh( (tmid @ V)[i,n] ) * w_att[n]
// d[i]      = tmid[i] @ (Wc[:,1]-Wc[:,0])
__global__ __launch_bounds__(256, 2)
void gemm2_fused(const float* __restrict__ Vm, const float* __restrict__ watt,
                 const float* __restrict__ Wc) {
    __shared__ __align__(16) float As[8][128];
    __shared__ __align__(16) float Bs[8][128];
    __shared__ float wds[8];
    __shared__ float red[128][17];
    const int tid = threadIdx.x;
    const int tx = tid & 15, ty = tid >> 4;
    const int row0 = blockIdx.x * 128;

    const int arow = tid >> 1;
    const int acol = (tid & 1) * 4;
    const int brow = tid >> 5;
    const int bcol = (tid & 31) * 4;
    const bool aval = (row0 + arow) < NROWS;

    float srow[8], dpart[8];
#pragma unroll
    for (int r = 0; r < 8; r++) { srow[r] = 0.f; dpart[r] = 0.f; }

    for (int nt = 0; nt < 4; nt++) {
        float acc[8][8];
#pragma unroll
        for (int r = 0; r < 8; r++)
#pragma unroll
            for (int c = 0; c < 8; c++) acc[r][c] = 0.f;
        float wv[8];
#pragma unroll
        for (int c = 0; c < 8; c++) wv[c] = watt[nt * 128 + tx * 8 + c];

        for (int kt = 0; kt < DD / 8; kt++) {
            float4 av = aval ? *(const float4*)&g_tmid[(size_t)(row0 + arow) * DD + kt * 8 + acol]
                             : make_float4(0.f, 0.f, 0.f, 0.f);
            As[acol + 0][arow] = av.x;
            As[acol + 1][arow] = av.y;
            As[acol + 2][arow] = av.z;
            As[acol + 3][arow] = av.w;
            *(float4*)&Bs[brow][bcol] =
                *(const float4*)&Vm[(size_t)(kt * 8 + brow) * DD + nt * 128 + bcol];
            if (nt == 0 && tid < 8)
                wds[tid] = Wc[(kt * 8 + tid) * 2 + 1] - Wc[(kt * 8 + tid) * 2];
            __syncthreads();
#pragma unroll
            for (int k = 0; k < 8; k++) {
                float ra[8], rb[8];
                *(float4*)&ra[0] = *(float4*)&As[k][ty * 8];
                *(float4*)&ra[4] = *(float4*)&As[k][ty * 8 + 4];
                *(float4*)&rb[0] = *(float4*)&Bs[k][tx * 8];
                *(float4*)&rb[4] = *(float4*)&Bs[k][tx * 8 + 4];
                if (nt == 0) {
                    float w = wds[k];
#pragma unroll
                    for (int r = 0; r < 8; r++) dpart[r] = fmaf(ra[r], w, dpart[r]);
                }
#pragma unroll
                for (int r = 0; r < 8; r++)
#pragma unroll
                    for (int c = 0; c < 8; c++)
                        acc[r][c] = fmaf(ra[r], rb[c], acc[r][c]);
            }
            __syncthreads();
        }
        // epilogue for this N tile
#pragma unroll
        for (int r = 0; r < 8; r++)
#pragma unroll
            for (int c = 0; c < 8; c++)
                srow[r] = fmaf(tanhf(acc[r][c]), wv[c], srow[r]);
    }

    // reduce srow across the 16 tx lanes sharing each row
#pragma unroll
    for (int r = 0; r < 8; r++) red[ty * 8 + r][tx] = srow[r];
    __syncthreads();
    if (tid < 128) {
        float s = 0.f;
#pragma unroll
        for (int j = 0; j < 16; j++) s += red[tid][j];
        int grow = row0 + tid;
        if (grow < NROWS) g_scores[grow] = s;
    }
    if (tx == 0) {
#pragma unroll
        for (int r = 0; r < 8; r++) {
            int grow = row0 + ty * 8 + r;
            if (grow < NROWS) g_d[grow] = dpart[r];
        }
    }
}

// ---------------- global softmax reductions ---------------------------------
__global__ void red_max_kernel() {
    __shared__ float sm[256];
    float m = -1e30f;
    for (int i = blockIdx.x * blockDim.x + threadIdx.x; i < NROWS;
         i += gridDim.x * blockDim.x)
        m = fmaxf(m, g_scores[i]);
    sm[threadIdx.x] = m;
    __syncthreads();
    for (int s = 128; s > 0; s >>= 1) {
        if (threadIdx.x < s) sm[threadIdx.x] = fmaxf(sm[threadIdx.x], sm[threadIdx.x + s]);
        __syncthreads();
    }
    if (threadIdx.x == 0) atomicMax(&g_maxbits, enc_f(sm[0]));
}

__global__ void red_sum_kernel() {
    __shared__ float sm[256];
    float smax = dec_f(g_maxbits);
    float acc = 0.f;
    for (int i = blockIdx.x * blockDim.x + threadIdx.x; i < NROWS;
         i += gridDim.x * blockDim.x)
        acc += expf(g_scores[i] - smax);
    sm[threadIdx.x] = acc;
    __syncthreads();
    for (int s = 128; s > 0; s >>= 1) {
        if (threadIdx.x < s) sm[threadIdx.x] += sm[threadIdx.x + s];
        __syncthreads();
    }
    if (threadIdx.x == 0) atomicAdd(&g_Z, sm[0]);
}

// ---------------- per-group re-softmax + argmax/argmin ----------------------
#define GITER 13  // ceil(12500/1024)
__global__ __launch_bounds__(1024, 1)
void group_kernel(const int* __restrict__ idx) {
    __shared__ float sv[1024];
    __shared__ int si[1024];
    const int g = blockIdx.x;
    const int tid = threadIdx.x;
    const float smax = dec_f(g_maxbits);
    const float Z = g_Z;

    float vals[GITER];
    int js[GITER];
    float lmax = -1e30f;
#pragma unroll
    for (int t = 0; t < GITER; t++) {
        int i = tid + t * 1024;
        if (i < GS) {
            int j = idx[g * GS + i];
            float a = expf(g_scores[j] - smax) / Z;   // AA[j]
            vals[t] = a;
            js[t] = j;
            lmax = fmaxf(lmax, a);
        } else {
            vals[t] = -1e30f;
            js[t] = 0;
        }
    }
    // reduce max of AA over group
    sv[tid] = lmax;
    __syncthreads();
    for (int s = 512; s > 0; s >>= 1) {
        if (tid < s) sv[tid] = fmaxf(sv[tid], sv[tid + s]);
        __syncthreads();
    }
    float m = sv[0];
    __syncthreads();
    // reduce sum exp(AA - m)
    float lsum = 0.f;
#pragma unroll
    for (int t = 0; t < GITER; t++) {
        int i = tid + t * 1024;
        if (i < GS) lsum += expf(vals[t] - m);
    }
    sv[tid] = lsum;
    __syncthreads();
    for (int s = 512; s > 0; s >>= 1) {
        if (tid < s) sv[tid] += sv[tid + s];
        __syncthreads();
    }
    float S = sv[0];
    __syncthreads();

    // tAA, q, per-thread argmax/argmin (first-index tie-break)
    float bq = -1e30f; int bi = GS;
    float wq =  1e30f; int wi = GS;
#pragma unroll
    for (int t = 0; t < GITER; t++) {
        int i = tid + t * 1024;
        if (i < GS) {
            float ta = expf(vals[t] - m) / S;
            g_tAA[g * GS + i] = ta;
            float q = ta * g_d[js[t]];
            if (q > bq || (q == bq && i < bi)) { bq = q; bi = i; }
            if (q < wq || (q == wq && i < wi)) { wq = q; wi = i; }
        }
    }
    // block argmax
    sv[tid] = bq; si[tid] = bi;
    __syncthreads();
    for (int s = 512; s > 0; s >>= 1) {
        if (tid < s) {
            float v2 = sv[tid + s]; int i2 = si[tid + s];
            if (v2 > sv[tid] || (v2 == sv[tid] && i2 < si[tid])) { sv[tid] = v2; si[tid] = i2; }
        }
        __syncthreads();
    }
    if (tid == 0) g_imax[g] = si[0];
    __syncthreads();
    // block argmin
    sv[tid] = wq; si[tid] = wi;
    __syncthreads();
    for (int s = 512; s > 0; s >>= 1) {
        if (tid < s) {
            float v2 = sv[tid + s]; int i2 = si[tid + s];
            if (v2 < sv[tid] || (v2 == sv[tid] && i2 < si[tid])) { sv[tid] = v2; si[tid] = i2; }
        }
        __syncthreads();
    }
    if (tid == 0) g_imin[g] = si[0];
}

// ---------------- bag = sum_i tAA_i * tmid[idx_i] ---------------------------
#define BPG 64
__global__ void bag_kernel(const int* __restrict__ idx) {
    const int g = blockIdx.y;
    const int blk = blockIdx.x;
    const int tid = threadIdx.x;  // 256
    const int CH = (GS + BPG - 1) / BPG;
    int i0 = blk * CH;
    int i1 = i0 + CH; if (i1 > GS) i1 = GS;
    float a0 = 0.f, a1 = 0.f;
    for (int i = i0; i < i1; i++) {
        int j = idx[g * GS + i];
        float w = g_tAA[g * GS + i];
        const float* row = &g_tmid[(size_t)j * DD];
        a0 = fmaf(w, row[tid], a0);
        a1 = fmaf(w, row[tid + 256], a1);
    }
    atomicAdd(&g_bag[g * DD + tid], a0);
    atomicAdd(&g_bag[g * DD + tid + 256], a1);
}

// ---------------- final: preds + pseudo feats --------------------------------
__global__ void final_kernel(const float* __restrict__ Wc, const float* __restrict__ bc,
                             float* __restrict__ out) {
    const int tid = threadIdx.x;  // 512
    const int w = tid >> 5, lane = tid & 31;
    if (w < 16) {
        int g = w >> 1, c = w & 1;
        float s = 0.f;
        for (int k = lane; k < DD; k += 32)
            s = fmaf(g_bag[g * DD + k], Wc[k * 2 + c], s);
#pragma unroll
        for (int o = 16; o > 0; o >>= 1) s += __shfl_down_sync(0xFFFFFFFFu, s, o);
        if (lane == 0) out[g * 2 + c] = s + bc[c];
    }
    // pseudo feats: global tmid indexed by LOCAL group indices (faithful quirk)
    for (int e = tid; e < NG * 2 * DD; e += 512) {
        int g = e / (2 * DD);
        int r = (e / DD) & 1;
        int c = e % DD;
        int rowi = r ? g_imin[g] : g_imax[g];
        out[16 + e] = g_tmid[(size_t)rowi * DD + c];
    }
}

// ---------------- launch ------------------------------------------------------
extern "C" void kernel_launch(void* const* d_in, const int* in_sizes, int n_in,
                              void* d_out, int out_size) {
    const float* x    = (const float*)d_in[0];
    const int*   idx  = (const int*)d_in[1];
    const float* W1   = (const float*)d_in[2];
    const float* V    = (const float*)d_in[3];
    const float* watt = (const float*)d_in[4];
    const float* Wc   = (const float*)d_in[5];
    const float* bc   = (const float*)d_in[6];
    float* out = (float*)d_out;

    const int mtiles = (NROWS + 127) / 128;

    init_kernel<<<16, 256>>>();
    gemm1_relu<<<dim3(mtiles, DD / 128), 256>>>(x, W1);
    gemm2_fused<<<mtiles, 256>>>(V, watt, Wc);
    red_max_kernel<<<256, 256>>>();
    red_sum_kernel<<<256, 256>>>();
    group_kernel<<<NG, 1024>>>(idx);
    bag_kernel<<<dim3(BPG, NG), 256>>>(idx);
    final_kernel<<<1, 512>>>(Wc, bc, out);
}

// round 3
// speedup vs baseline: 1.8994x; 1.8994x over previous
#include <cuda_runtime.h>
#include <cuda_bf16.h>
#include <mma.h>
#include <cstdint>

using namespace nvcuda;

// Problem constants
#define NROWS 100000
#define DIN   1024
#define DD    512
#define NG    8
#define GS    12500

// GEMM tiling
#define BM 128
#define BN 128
#define BK 16
#define LDA 24      // As stride (bf16 elems), 48B
#define LDB 136     // Bs stride (bf16 elems), 272B
#define LDCS 68     // epilogue staging stride (fp32 elems), 272B
#define A_BYTES (BM * LDA * 2)          // 6144
#define B_BYTES (BK * LDB * 2)          // 4352
#define BUFB (2 * A_BYTES + 2 * B_BYTES) // 20992
#define SMEM_BYTES (2 * BUFB)            // 41984 (< 48KB default)
#define MTILES ((NROWS + BM - 1) / BM)   // 782

// ---------------- scratch (device globals; no allocation allowed) ----------
__device__ float    g_tmid[(size_t)NROWS * DD];   // 204.8 MB
__device__ float    g_scores[NROWS];
__device__ float    g_d[NROWS];
__device__ float    g_spart[4 * NROWS];
__device__ float    g_dpart[4 * NROWS];
__device__ float    g_tAA[NG * GS];
__device__ float    g_bag[NG * DD];
__device__ unsigned g_maxbits;
__device__ float    g_Z;
__device__ int      g_imax[NG];
__device__ int      g_imin[NG];

// ---------------- helpers ---------------------------------------------------
__device__ __forceinline__ float tanh_fast(float x) {
    float y;
    asm("tanh.approx.f32 %0, %1;" : "=f"(y) : "f"(x));
    return y;
}
// fp32x8 -> bf16 hi/lo split, 16B stores
__device__ __forceinline__ void split_sts(float4 v0, float4 v1,
                                          __nv_bfloat16* h, __nv_bfloat16* l) {
    float v[8] = {v0.x, v0.y, v0.z, v0.w, v1.x, v1.y, v1.z, v1.w};
    __nv_bfloat16 hv[8], lv[8];
#pragma unroll
    for (int j = 0; j < 8; j++) {
        hv[j] = __float2bfloat16(v[j]);
        lv[j] = __float2bfloat16(v[j] - __bfloat162float(hv[j]));
    }
    *(uint4*)h = *(uint4*)hv;
    *(uint4*)l = *(uint4*)lv;
}
// ordered-float encoding for atomicMax over signed floats
__device__ __forceinline__ unsigned enc_f(float f) {
    unsigned u = __float_as_uint(f);
    return (u & 0x80000000u) ? ~u : (u | 0x80000000u);
}
__device__ __forceinline__ float dec_f(unsigned u) {
    u = (u & 0x80000000u) ? (u & 0x7FFFFFFFu) : ~u;
    return __uint_as_float(u);
}

// ---------------- init -------------------------------------------------------
__global__ void init_kernel() {
    int tid = blockIdx.x * blockDim.x + threadIdx.x;
    if (tid == 0) { g_maxbits = 0u; g_Z = 0.f; }
    if (tid < NG * DD) g_bag[tid] = 0.f;
}

// ---------------- bf16x3 WMMA GEMM ------------------------------------------
// MODE 0: C = Ain[ NROWS x KTOT ] @ Bin[ KTOT x 512 ]; epilogue: relu -> g_tmid,
//         dpart[by][row] = relu(C_row) . (Wc[:,1]-Wc[:,0]) over this n-tile.
// MODE 1: A = g_tmid; epilogue: spart[by][row] = sum_n tanh(C[row,n])*watt[n].
template <int KTOT, int MODE>
__global__ void __launch_bounds__(256, 2)
gemm_mma(const float* __restrict__ Ain, const float* __restrict__ Bin,
         const float* __restrict__ watt, const float* __restrict__ Wc) {
    extern __shared__ char dsm[];
    const float* A = (MODE == 0) ? Ain : (const float*)g_tmid;

    const int tid = threadIdx.x;
    const int wid = tid >> 5;
    const int m0 = blockIdx.x * BM;
    const int n0 = blockIdx.y * BN;

    // accumulators: warp tile 32x64 -> 2 (M) x 4 (N) frags
    wmma::fragment<wmma::accumulator, 16, 16, 16, float> acc[2][4];
#pragma unroll
    for (int i = 0; i < 2; i++)
#pragma unroll
        for (int n = 0; n < 4; n++) wmma::fill_fragment(acc[i][n], 0.f);

    // staging maps
    const int ar  = tid >> 1;            // A row 0..127
    const int akq = (tid & 1) * 8;       // A k offset 0/8
    const int bk  = tid >> 4;            // B k row 0..15
    const int bnq = (tid & 15) * 8;      // B n offset 0..120
    const bool aval = (m0 + ar) < NROWS;

    const float* aptr = A + (size_t)(m0 + ar) * KTOT + akq;
    const float* bptr = Bin + (size_t)bk * DD + n0 + bnq;

    const int wm = (wid >> 1) * 32;
    const int wn = (wid & 1) * 64;

    float4 pa0, pa1, pb0, pb1;
    pa0 = aval ? *(const float4*)aptr : make_float4(0.f, 0.f, 0.f, 0.f);
    pa1 = aval ? *(const float4*)(aptr + 4) : make_float4(0.f, 0.f, 0.f, 0.f);
    pb0 = *(const float4*)bptr;
    pb1 = *(const float4*)(bptr + 4);

    const int KC = KTOT / BK;
    for (int kc = 0; kc < KC; kc++) {
        char* buf = dsm + (kc & 1) * BUFB;
        __nv_bfloat16* Ah = (__nv_bfloat16*)buf;
        __nv_bfloat16* Al = (__nv_bfloat16*)(buf + A_BYTES);
        __nv_bfloat16* Bh = (__nv_bfloat16*)(buf + 2 * A_BYTES);
        __nv_bfloat16* Bl = (__nv_bfloat16*)(buf + 2 * A_BYTES + B_BYTES);

        split_sts(pa0, pa1, &Ah[ar * LDA + akq], &Al[ar * LDA + akq]);
        split_sts(pb0, pb1, &Bh[bk * LDB + bnq], &Bl[bk * LDB + bnq]);
        __syncthreads();

        if (kc + 1 < KC) {
            aptr += BK;
            bptr += (size_t)BK * DD;
            if (aval) {
                pa0 = *(const float4*)aptr;
                pa1 = *(const float4*)(aptr + 4);
            }
            pb0 = *(const float4*)bptr;
            pb1 = *(const float4*)(bptr + 4);
        }

#pragma unroll
        for (int n = 0; n < 4; n++) {
            wmma::fragment<wmma::matrix_b, 16, 16, 16, __nv_bfloat16, wmma::row_major> fbh, fbl;
            wmma::load_matrix_sync(fbh, &Bh[wn + 16 * n], LDB);
            wmma::load_matrix_sync(fbl, &Bl[wn + 16 * n], LDB);
#pragma unroll
            for (int i = 0; i < 2; i++) {
                wmma::fragment<wmma::matrix_a, 16, 16, 16, __nv_bfloat16, wmma::row_major> fah, fal;
                wmma::load_matrix_sync(fah, &Ah[(wm + 16 * i) * LDA], LDA);
                wmma::load_matrix_sync(fal, &Al[(wm + 16 * i) * LDA], LDA);
                wmma::mma_sync(acc[i][n], fah, fbh, acc[i][n]);
                wmma::mma_sync(acc[i][n], fal, fbh, acc[i][n]);
                wmma::mma_sync(acc[i][n], fah, fbl, acc[i][n]);
            }
        }
    }

    // ---------------- epilogue: stage C in two 64-col halves ----------------
    float* Cs = (float*)dsm;
    const int row = tid >> 1;
    const int q = tid & 1;
    const int grow = m0 + row;
    float racc = 0.f;  // dacc (MODE 0) or sacc (MODE 1)

#pragma unroll
    for (int hn = 0; hn < 2; hn++) {
        __syncthreads();
        if ((wid & 1) == hn) {
#pragma unroll
            for (int i = 0; i < 2; i++)
#pragma unroll
                for (int n = 0; n < 4; n++)
                    wmma::store_matrix_sync(&Cs[(wm + 16 * i) * LDCS + 16 * n],
                                            acc[i][n], LDCS, wmma::mem_row_major);
        }
        __syncthreads();
        if (grow < NROWS) {
            const int cbase = n0 + hn * 64 + q * 32;
            if (MODE == 0) {
#pragma unroll
                for (int j = 0; j < 32; j += 4) {
                    float4 v = *(float4*)&Cs[row * LDCS + q * 32 + j];
                    v.x = fmaxf(v.x, 0.f); v.y = fmaxf(v.y, 0.f);
                    v.z = fmaxf(v.z, 0.f); v.w = fmaxf(v.w, 0.f);
                    *(float4*)&g_tmid[(size_t)grow * DD + cbase + j] = v;
                    int c = cbase + j;
                    racc = fmaf(v.x, Wc[2 * c + 2 * 0 + 1] - Wc[2 * c + 0], racc);
                    racc = fmaf(v.y, Wc[2 * (c + 1) + 1] - Wc[2 * (c + 1)], racc);
                    racc = fmaf(v.z, Wc[2 * (c + 2) + 1] - Wc[2 * (c + 2)], racc);
                    racc = fmaf(v.w, Wc[2 * (c + 3) + 1] - Wc[2 * (c + 3)], racc);
                }
            } else {
#pragma unroll
                for (int j = 0; j < 32; j++) {
                    float y = Cs[row * LDCS + q * 32 + j];
                    racc = fmaf(tanh_fast(y), watt[cbase + j], racc);
                }
            }
        }
    }
    racc += __shfl_xor_sync(0xFFFFFFFFu, racc, 1);
    if (q == 0 && grow < NROWS) {
        if (MODE == 0)
            g_dpart[(size_t)blockIdx.y * NROWS + grow] = racc;
        else
            g_spart[(size_t)blockIdx.y * NROWS + grow] = racc;
    }
}

// ---------------- combine partials -------------------------------------------
__global__ void combine_kernel() {
    int i = blockIdx.x * blockDim.x + threadIdx.x;
    if (i < NROWS) {
        g_d[i] = ((g_dpart[i] + g_dpart[NROWS + i]) +
                  (g_dpart[2 * NROWS + i] + g_dpart[3 * NROWS + i]));
        g_scores[i] = ((g_spart[i] + g_spart[NROWS + i]) +
                       (g_spart[2 * NROWS + i] + g_spart[3 * NROWS + i]));
    }
}

// ---------------- global softmax reductions ---------------------------------
__global__ void red_max_kernel() {
    __shared__ float sm[256];
    float m = -1e30f;
    for (int i = blockIdx.x * blockDim.x + threadIdx.x; i < NROWS;
         i += gridDim.x * blockDim.x)
        m = fmaxf(m, g_scores[i]);
    sm[threadIdx.x] = m;
    __syncthreads();
    for (int s = 128; s > 0; s >>= 1) {
        if (threadIdx.x < s) sm[threadIdx.x] = fmaxf(sm[threadIdx.x], sm[threadIdx.x + s]);
        __syncthreads();
    }
    if (threadIdx.x == 0) atomicMax(&g_maxbits, enc_f(sm[0]));
}

__global__ void red_sum_kernel() {
    __shared__ float sm[256];
    float smax = dec_f(g_maxbits);
    float acc = 0.f;
    for (int i = blockIdx.x * blockDim.x + threadIdx.x; i < NROWS;
         i += gridDim.x * blockDim.x)
        acc += expf(g_scores[i] - smax);
    sm[threadIdx.x] = acc;
    __syncthreads();
    for (int s = 128; s > 0; s >>= 1) {
        if (threadIdx.x < s) sm[threadIdx.x] += sm[threadIdx.x + s];
        __syncthreads();
    }
    if (threadIdx.x == 0) atomicAdd(&g_Z, sm[0]);
}

// ---------------- per-group re-softmax + argmax/argmin ----------------------
#define GITER 13  // ceil(12500/1024)
__global__ __launch_bounds__(1024, 1)
void group_kernel(const int* __restrict__ idx) {
    __shared__ float sv[1024];
    __shared__ int si[1024];
    const int g = blockIdx.x;
    const int tid = threadIdx.x;
    const float smax = dec_f(g_maxbits);
    const float Z = g_Z;

    float vals[GITER];
    int js[GITER];
    float lmax = -1e30f;
#pragma unroll
    for (int t = 0; t < GITER; t++) {
        int i = tid + t * 1024;
        if (i < GS) {
            int j = idx[g * GS + i];
            float a = expf(g_scores[j] - smax) / Z;   // AA[j]
            vals[t] = a;
            js[t] = j;
            lmax = fmaxf(lmax, a);
        } else {
            vals[t] = -1e30f;
            js[t] = 0;
        }
    }
    sv[tid] = lmax;
    __syncthreads();
    for (int s = 512; s > 0; s >>= 1) {
        if (tid < s) sv[tid] = fmaxf(sv[tid], sv[tid + s]);
        __syncthreads();
    }
    float m = sv[0];
    __syncthreads();
    float lsum = 0.f;
#pragma unroll
    for (int t = 0; t < GITER; t++) {
        int i = tid + t * 1024;
        if (i < GS) lsum += expf(vals[t] - m);
    }
    sv[tid] = lsum;
    __syncthreads();
    for (int s = 512; s > 0; s >>= 1) {
        if (tid < s) sv[tid] += sv[tid + s];
        __syncthreads();
    }
    float S = sv[0];
    __syncthreads();

    float bq = -1e30f; int bi = GS;
    float wq =  1e30f; int wi = GS;
#pragma unroll
    for (int t = 0; t < GITER; t++) {
        int i = tid + t * 1024;
        if (i < GS) {
            float ta = expf(vals[t] - m) / S;
            g_tAA[g * GS + i] = ta;
            float qv = ta * g_d[js[t]];
            if (qv > bq || (qv == bq && i < bi)) { bq = qv; bi = i; }
            if (qv < wq || (qv == wq && i < wi)) { wq = qv; wi = i; }
        }
    }
    sv[tid] = bq; si[tid] = bi;
    __syncthreads();
    for (int s = 512; s > 0; s >>= 1) {
        if (tid < s) {
            float v2 = sv[tid + s]; int i2 = si[tid + s];
            if (v2 > sv[tid] || (v2 == sv[tid] && i2 < si[tid])) { sv[tid] = v2; si[tid] = i2; }
        }
        __syncthreads();
    }
    if (tid == 0) g_imax[g] = si[0];
    __syncthreads();
    sv[tid] = wq; si[tid] = wi;
    __syncthreads();
    for (int s = 512; s > 0; s >>= 1) {
        if (tid < s) {
            float v2 = sv[tid + s]; int i2 = si[tid + s];
            if (v2 < sv[tid] || (v2 == sv[tid] && i2 < si[tid])) { sv[tid] = v2; si[tid] = i2; }
        }
        __syncthreads();
    }
    if (tid == 0) g_imin[g] = si[0];
}

// ---------------- bag = sum_i tAA_i * tmid[idx_i] ---------------------------
#define BPG 64
__global__ void bag_kernel(const int* __restrict__ idx) {
    const int g = blockIdx.y;
    const int blk = blockIdx.x;
    const int tid = threadIdx.x;  // 256
    const int CH = (GS + BPG - 1) / BPG;
    int i0 = blk * CH;
    int i1 = i0 + CH; if (i1 > GS) i1 = GS;
    float a0 = 0.f, a1 = 0.f;
    for (int i = i0; i < i1; i++) {
        int j = idx[g * GS + i];
        float w = g_tAA[g * GS + i];
        const float* row = &g_tmid[(size_t)j * DD];
        a0 = fmaf(w, row[tid], a0);
        a1 = fmaf(w, row[tid + 256], a1);
    }
    atomicAdd(&g_bag[g * DD + tid], a0);
    atomicAdd(&g_bag[g * DD + tid + 256], a1);
}

// ---------------- final: preds + pseudo feats --------------------------------
__global__ void final_kernel(const float* __restrict__ Wc, const float* __restrict__ bc,
                             float* __restrict__ out) {
    const int tid = threadIdx.x;  // 512
    const int w = tid >> 5, lane = tid & 31;
    if (w < 16) {
        int g = w >> 1, c = w & 1;
        float s = 0.f;
        for (int k = lane; k < DD; k += 32)
            s = fmaf(g_bag[g * DD + k], Wc[k * 2 + c], s);
#pragma unroll
        for (int o = 16; o > 0; o >>= 1) s += __shfl_down_sync(0xFFFFFFFFu, s, o);
        if (lane == 0) out[g * 2 + c] = s + bc[c];
    }
    for (int e = tid; e < NG * 2 * DD; e += 512) {
        int g = e / (2 * DD);
        int r = (e / DD) & 1;
        int c = e % DD;
        int rowi = r ? g_imin[g] : g_imax[g];
        out[16 + e] = g_tmid[(size_t)rowi * DD + c];
    }
}

// ---------------- launch ------------------------------------------------------
extern "C" void kernel_launch(void* const* d_in, const int* in_sizes, int n_in,
                              void* d_out, int out_size) {
    const float* x    = (const float*)d_in[0];
    const int*   idx  = (const int*)d_in[1];
    const float* W1   = (const float*)d_in[2];
    const float* V    = (const float*)d_in[3];
    const float* watt = (const float*)d_in[4];
    const float* Wc   = (const float*)d_in[5];
    const float* bc   = (const float*)d_in[6];
    float* out = (float*)d_out;

    init_kernel<<<16, 256>>>();
    gemm_mma<DIN, 0><<<dim3(MTILES, 4), 256, SMEM_BYTES>>>(x, W1, watt, Wc);
    gemm_mma<DD, 1><<<dim3(MTILES, 4), 256, SMEM_BYTES>>>(x, V, watt, Wc);
    combine_kernel<<<(NROWS + 255) / 256, 256>>>();
    red_max_kernel<<<256, 256>>>();
    red_sum_kernel<<<256, 256>>>();
    group_kernel<<<NG, 1024>>>(idx);
    bag_kernel<<<dim3(BPG, NG), 256>>>(idx);
    final_kernel<<<1, 512>>>(Wc, bc, out);
}